// round 13
// baseline (speedup 1.0000x reference)
#include <cuda_runtime.h>
#include <math.h>
#include <stdint.h>

#define BB 2
#define TT 2048
#define DIMM 1024
#define HH 16
#define DHH 64
#define M_TOT (BB*TT)        /* 4096 */

// Scratch (static device globals; allocation is forbidden)
__device__ float g_q[(size_t)BB*HH*TT*DHH];   // [b,h,t,d]   natural d (rope fused in attn)
__device__ float g_k[(size_t)BB*HH*TT*DHH];   // [b,h,t,d']  (d k-permuted by rope_k)
__device__ float g_v[(size_t)BB*HH*TT*DHH];   // [b,h,d,t]   TRANSPOSED, natural d
__device__ float g_y[(size_t)BB*HH*TT*DHH];   // [b,h,t,d']  (d k-permuted)
__device__ float g_xr[(size_t)M_TOT*DIMM];    // x rounded+k-permuted
__device__ float g_wtq[(size_t)3072*1024];    // W_qkv^T [n][k'] rounded+perm
__device__ float g_wto[(size_t)1024*1024];    // W_out^T [n][k'] rounded+perm
__device__ float g_rc[TT*32];                 // rope cos table
__device__ float g_rs[TT*32];                 // rope sin table

// 1/8 softmax scale folded with log2(e) for exp2-domain softmax
#define QSCALE 0.18033688068352986f

// k-permutation within 8-blocks: thread tg's pair (tg, tg+4) -> (2tg, 2tg+1)
__host__ __device__ __forceinline__ int kperm8(int j) {
    return ((j & 3) << 1) | (j >> 2);
}

// ---------------------------------------------------------------------------
// Helpers (legacy mma.sync tf32; tcgen05 needs the sm_103a feature target
// which this harness does not emit).
// ---------------------------------------------------------------------------
__device__ __forceinline__ uint32_t smem_u32(const void* p) {
    uint32_t a;
    asm("{ .reg .u64 t; cvta.to.shared.u64 t, %1; cvt.u32.u64 %0, t; }"
        : "=r"(a) : "l"(p));
    return a;
}
__device__ __forceinline__ uint32_t cvt_tf32(float f) {
    uint32_t u;
    asm("cvt.rna.tf32.f32 %0, %1;" : "=r"(u) : "f"(f));
    return u;
}
__device__ __forceinline__ float rnd_tf32(float f) {
    return __uint_as_float(cvt_tf32(f));
}
#define CP16(sa, gp) \
    asm volatile("cp.async.cg.shared.global [%0], [%1], 16;" :: "r"(sa), "l"(gp))
#define CP_COMMIT() asm volatile("cp.async.commit_group;" ::: "memory")
#define CP_WAIT2()  asm volatile("cp.async.wait_group 2;" ::: "memory")
#define CP_WAIT1()  asm volatile("cp.async.wait_group 1;" ::: "memory")
#define CP_WAIT0()  asm volatile("cp.async.wait_group 0;" ::: "memory")

__device__ __forceinline__ void mma_tf32(float* c, const uint32_t* a,
                                         const uint32_t* b) {
    asm volatile(
        "mma.sync.aligned.m16n8k8.row.col.f32.tf32.tf32.f32 "
        "{%0,%1,%2,%3}, {%4,%5,%6,%7}, {%8,%9}, {%0,%1,%2,%3};"
        : "+f"(c[0]), "+f"(c[1]), "+f"(c[2]), "+f"(c[3])
        : "r"(a[0]), "r"(a[1]), "r"(a[2]), "r"(a[3]), "r"(b[0]), "r"(b[1]));
}

// ---------------------------------------------------------------------------
// Fused prep: round_x (2048 blocks) | transpose W_qkv (3072) |
// transpose W_out (1024) | build_rope (256). All independent.
// ---------------------------------------------------------------------------
__global__ void prep_all(const float* __restrict__ x,
                         const float* __restrict__ Wq,
                         const float* __restrict__ Wo)
{
    __shared__ float t[32][33];
    const int b = blockIdx.x;
    const int tid = threadIdx.x;

    if (b < 2048) {                      // ---- round_x + k-permute ----
        const int i = b * 256 + tid;
        float4 a = ((const float4*)x)[2 * i];
        float4 c = ((const float4*)x)[2 * i + 1];
        float4 o0 = make_float4(rnd_tf32(a.x), rnd_tf32(c.x), rnd_tf32(a.y), rnd_tf32(c.y));
        float4 o1 = make_float4(rnd_tf32(a.z), rnd_tf32(c.z), rnd_tf32(a.w), rnd_tf32(c.w));
        ((float4*)g_xr)[2 * i] = o0;
        ((float4*)g_xr)[2 * i + 1] = o1;
    } else if (b < 2048 + 3072 + 1024) { // ---- weight transpose+round+perm ----
        const float* src;
        float* dst;
        int C, c0, r0;
        if (b < 2048 + 3072) {
            const int bb = b - 2048;
            src = Wq; dst = g_wtq; C = 3072;
            c0 = (bb % 96) * 32; r0 = (bb / 96) * 32;
        } else {
            const int bb = b - 2048 - 3072;
            src = Wo; dst = g_wto; C = 1024;
            c0 = (bb % 32) * 32; r0 = (bb / 32) * 32;
        }
        const int tx = tid & 31, ty = tid >> 5;
        for (int i = ty; i < 32; i += 8)
            t[i][tx] = src[(size_t)(r0 + i) * C + c0 + tx];
        __syncthreads();
        const int kp = (tx & 24) | kperm8(tx & 7);
        for (int i = ty; i < 32; i += 8)
            dst[(size_t)(c0 + i) * 1024 + r0 + kp] = rnd_tf32(t[tx][i]);
    } else {                             // ---- build rope table (fp64) ----
        const int idx = (b - 6144) * 256 + tid;
        const int d = idx & 31, tt = idx >> 5;
        const float invf = (float)exp(-(double)d * (log(10000.0) / 32.0));
        const float ang = (float)tt * invf;
        double sd, cd;
        sincos((double)ang, &sd, &cd);
        g_rc[tt * 32 + d] = (float)cd;
        g_rs[tt * 32 + d] = (float)sd;
    }
}

// ---------------------------------------------------------------------------
// mma.sync tf32 GEMM, CTA 128x128, BK=32, 8 warps, warp 64x32.
// XOR-swizzled SMEM, 3-stage cp.async pipeline (unchanged from R12).
// ---------------------------------------------------------------------------
#define ATILE 16384                       /* 128*32*4 bytes */
#define STAGE (2 * ATILE)                 /* A + B */
#define GEMM_SMEM (3 * STAGE)             /* 98304 */

template <int MODE>
__global__ __launch_bounds__(256) void gemm_mma(
    const float* __restrict__ A, const float* __restrict__ Bt,
    const float* __restrict__ bias, float* __restrict__ out)
{
    extern __shared__ char smem[];
    const uint32_t sb = smem_u32(smem);
    const int tid = threadIdx.x;
    const int wid = tid >> 5;
    const int lane = tid & 31;
    const int gid = lane >> 2;
    const int tg = lane & 3;
    const int mb = (wid >> 2) * 64;
    const int nb = (wid & 3) * 32;
    const int m0 = blockIdx.y * 128;
    const int n0 = blockIdx.x * 128;
    const int sg = gid & 3;               // swizzle group selector

    float acc[4][4][4];
#pragma unroll
    for (int mf = 0; mf < 4; mf++)
#pragma unroll
        for (int nf = 0; nf < 4; nf++)
#pragma unroll
            for (int i = 0; i < 4; i++) acc[mf][nf][i] = 0.f;

    auto issue_tile = [&](int c) {
        const int p = c % 3;
        const int k0 = c * 32;
        const uint32_t aBase = sb + p * STAGE;
        const uint32_t bBase = aBase + ATILE;
#pragma unroll
        for (int i = 0; i < 4; i++) {
            const int e = tid + 256 * i;
            const int rr = e >> 3, q = e & 7;
            const uint32_t w = (uint32_t)(rr * 32 + (((q >> 1) ^ (rr & 3)) << 3)
                                          + (q & 1) * 4);
            const float* gp;
            if (MODE == 0) {
                gp = &A[(size_t)(m0 + rr) * 1024 + k0 + q * 4];
            } else {
                const int m = m0 + rr, b = m >> 11, t = m & (TT - 1);
                const int kk = k0 + q * 4, h = kk >> 6, d = kk & 63;
                gp = &g_y[(((size_t)b * HH + h) * TT + t) * DHH + d];
            }
            CP16(aBase + w * 4, gp);
        }
#pragma unroll
        for (int i = 0; i < 4; i++) {
            const int e = tid + 256 * i;
            const int rr = e >> 3, q = e & 7;
            const uint32_t w = (uint32_t)(rr * 32 + (((q >> 1) ^ (rr & 3)) << 3)
                                          + (q & 1) * 4);
            const float* gp = &Bt[(size_t)(n0 + rr) * 1024 + k0 + q * 4];
            CP16(bBase + w * 4, gp);
        }
        CP_COMMIT();
    };

    issue_tile(0);
    issue_tile(1);
    for (int c = 0; c < 32; c++) {
        if (c + 2 < 32)      { issue_tile(c + 2); CP_WAIT2(); }
        else if (c + 1 < 32) { CP_WAIT1(); }
        else                 { CP_WAIT0(); }
        __syncthreads();

        const int p = c % 3;
        const uint32_t* As = (const uint32_t*)(smem + p * STAGE);
        const uint32_t* Bs = (const uint32_t*)(smem + p * STAGE + ATILE);
#pragma unroll
        for (int ks = 0; ks < 4; ks++) {
            const int xo = ((ks ^ sg) << 3) + 2 * tg;
            uint32_t af[4][4], bf[4][2];
#pragma unroll
            for (int mf = 0; mf < 4; mf++) {
                const uint32_t* ap = As + (mb + mf * 16 + gid) * 32 + xo;
                uint2 lo = *(const uint2*)ap;
                uint2 hi = *(const uint2*)(ap + 256);
                af[mf][0] = lo.x; af[mf][2] = lo.y;
                af[mf][1] = hi.x; af[mf][3] = hi.y;
            }
#pragma unroll
            for (int nf = 0; nf < 4; nf++) {
                const uint32_t* bp = Bs + (nb + nf * 8 + gid) * 32 + xo;
                uint2 v = *(const uint2*)bp;
                bf[nf][0] = v.x; bf[nf][1] = v.y;
            }
#pragma unroll
            for (int mf = 0; mf < 4; mf++)
#pragma unroll
                for (int nf = 0; nf < 4; nf++)
                    mma_tf32(acc[mf][nf], af[mf], bf[nf]);
        }
        __syncthreads();
    }

#pragma unroll
    for (int mf = 0; mf < 4; mf++) {
        const int r0 = m0 + mb + mf * 16 + gid;
#pragma unroll
        for (int nf = 0; nf < 4; nf++) {
            const int n = n0 + nb + nf * 8 + tg * 2;
            const float bx = bias[n], by = bias[n + 1];
            float2 v0 = make_float2(acc[mf][nf][0] + bx, acc[mf][nf][1] + by);
            float2 v1 = make_float2(acc[mf][nf][2] + bx, acc[mf][nf][3] + by);
            if (MODE == 0) {
                const int which = n >> 10;
                const int rr = n & 1023;
                const int h = rr >> 6, d = rr & 63;
                const int b0i = r0 >> 11, t0i = r0 & (TT - 1);
                const int m1 = r0 + 8;
                const int b1i = m1 >> 11, t1i = m1 & (TT - 1);
                if (which == 2) {
                    const size_t vb0 = ((size_t)b0i * HH + h) * DHH;
                    const size_t vb1 = ((size_t)b1i * HH + h) * DHH;
                    g_v[(vb0 + d    ) * TT + t0i] = rnd_tf32(v0.x);
                    g_v[(vb0 + d + 1) * TT + t0i] = rnd_tf32(v0.y);
                    g_v[(vb1 + d    ) * TT + t1i] = rnd_tf32(v1.x);
                    g_v[(vb1 + d + 1) * TT + t1i] = rnd_tf32(v1.y);
                } else {
                    float* dst = (which == 0) ? g_q : g_k;
                    *(float2*)&dst[(((size_t)b0i * HH + h) * TT + t0i) * DHH + d] = v0;
                    *(float2*)&dst[(((size_t)b1i * HH + h) * TT + t1i) * DHH + d] = v1;
                }
            } else {
                *(float2*)&out[(size_t)r0 * DIMM + n] = v0;
                *(float2*)&out[(size_t)(r0 + 8) * DIMM + n] = v1;
            }
        }
    }
}

// ---------------------------------------------------------------------------
// RoPE on K only (q rope fused into attention).
// ---------------------------------------------------------------------------
__global__ void rope_k()
{
    const int idx = blockIdx.x * blockDim.x + threadIdx.x;   // 2^21
    const int d  = idx & 31;
    const int t  = (idx >> 5) & (TT - 1);
    const int bh = idx >> 16;
    const float cf = g_rc[t * 32 + d];
    const float sf = g_rs[t * 32 + d];
    const int dp = (d & 24) | kperm8(d & 7);

    const size_t base = ((size_t)bh * TT + t) * DHH;
    const float ka = g_k[base + d], kb = g_k[base + 32 + d];
    g_k[base + dp]      = rnd_tf32(ka * cf - kb * sf);
    g_k[base + 32 + dp] = rnd_tf32(ka * sf + kb * cf);
}

// ---------------------------------------------------------------------------
// Flash attention, mma.sync tf32, cp.async double-buffered K/V.
// 4 warps x 32 Q-rows (128 threads/CTA): every K/V fragment LDS.64 feeds
// TWO MMAs (LDS/MMA 1.125 -> 0.625). Same 128-row Q-tile, same SMEM,
// 2 CTAs/SM, one wave (paired q-tiles). Arithmetic order per row identical
// to R12 -> bit-identical result.
// ---------------------------------------------------------------------------
#define QPAD 72
#define VPAD 72
#define OFF_QH 0
#define OFF_KS (128*QPAD)
#define OFF_VS (OFF_KS + 2*64*QPAD)
#define ATTN_SMEM ((OFF_VS + 2*64*VPAD) * 4)   /* 110592 */

__global__ __launch_bounds__(128, 2) void attn_mma()
{
    extern __shared__ float sm[];
    uint32_t* Qh = (uint32_t*)sm + OFF_QH;
    const uint32_t sb = smem_u32(sm);

    const int bh = blockIdx.y;
    const int tid = threadIdx.x;
    const int wid = tid >> 5;             // 0..3
    const int lane = tid & 31;
    const int gid = lane >> 2;
    const int tg = lane & 3;
    const int wrow = wid * 32;            // warp owns 32 Q rows

    const float* Kg = g_k + (size_t)bh * TT * DHH;
    const float* Vg = g_v + (size_t)bh * DHH * TT;   // [d][t]

    const int p0 = kperm8(2 * tg), p1 = kperm8(2 * tg + 1);

#pragma unroll 1
    for (int pass = 0; pass < 2; pass++) {
        const int qt = pass == 0 ? (15 - (int)blockIdx.x) : (int)blockIdx.x;
        const int q0 = qt * 128;
        const float* Qg = g_q + ((size_t)bh * TT + q0) * DHH;

        // Load Q natural, fused RoPE (table), scale, cvt, store d-permuted
#pragma unroll
        for (int i = 0; i < 8; i++) {
            const int e = tid + 128 * i;        // 0..1023
            const int r = e >> 3, j = e & 7;
            const int d0 = j * 4;
            const int t = q0 + r;
            float4 qa = *(const float4*)&Qg[r * DHH + d0];
            float4 qb = *(const float4*)&Qg[r * DHH + 32 + d0];
            float4 cs = *(const float4*)&g_rc[t * 32 + d0];
            float4 sn = *(const float4*)&g_rs[t * 32 + d0];
            float lo[4] = {qa.x * cs.x - qb.x * sn.x, qa.y * cs.y - qb.y * sn.y,
                           qa.z * cs.z - qb.z * sn.z, qa.w * cs.w - qb.w * sn.w};
            float hi[4] = {qa.x * sn.x + qb.x * cs.x, qa.y * sn.y + qb.y * cs.y,
                           qa.z * sn.z + qb.z * cs.z, qa.w * sn.w + qb.w * cs.w};
#pragma unroll
            for (int u = 0; u < 4; u++) {
                const int dd = d0 + u;
                const int dp = (dd & 24) | kperm8(dd & 7);
                Qh[r * QPAD + dp]      = cvt_tf32(lo[u] * QSCALE);
                Qh[r * QPAD + 32 + dp] = cvt_tf32(hi[u] * QSCALE);
            }
        }

        float oacc[2][8][4];
#pragma unroll
        for (int mf = 0; mf < 2; mf++)
#pragma unroll
            for (int nf = 0; nf < 8; nf++)
#pragma unroll
                for (int i = 0; i < 4; i++) oacc[mf][nf][i] = 0.f;
        float mv[4] = {-INFINITY, -INFINITY, -INFINITY, -INFINITY};
        float lv[4] = {0.f, 0.f, 0.f, 0.f};

        // global row ids: frag mf half0 = q0+wrow+mf*16+gid, half1 = +8
        const int nkt = 2 * qt + 2;

        auto issue = [&](int kt) {
            const int st = kt & 1;
            const uint32_t kb = sb + (OFF_KS + st * 64 * QPAD) * 4;
            const uint32_t vb = sb + (OFF_VS + st * 64 * VPAD) * 4;
#pragma unroll
            for (int i = 0; i < 8; i++) {
                const int e = tid + 128 * i;
                const int r = e >> 4, c = (e & 15) * 4;
                CP16(kb + (uint32_t)(r * QPAD + c) * 4,
                     &Kg[(size_t)(kt * 64 + r) * DHH + c]);
                CP16(vb + (uint32_t)(r * VPAD + c) * 4,
                     &Vg[(size_t)r * TT + kt * 64 + c]);
            }
            CP_COMMIT();
        };

        issue(0);
        for (int kt = 0; kt < nkt; kt++) {
            if (kt + 1 < nkt) { issue(kt + 1); CP_WAIT1(); }
            else              { CP_WAIT0(); }
            __syncthreads();

            if (kt * 64 <= q0 + wrow + 31) {
                const int st = kt & 1;
                const uint32_t* Ks = (const uint32_t*)sm + OFF_KS + st * 64 * QPAD;
                const uint32_t* Vs = (const uint32_t*)sm + OFF_VS + st * 64 * VPAD;

                // ---- S = Q K^T : K frags shared across 2 m-frags ----
                float sacc[2][8][4];
#pragma unroll
                for (int mf = 0; mf < 2; mf++)
#pragma unroll
                    for (int nf = 0; nf < 8; nf++)
#pragma unroll
                        for (int i = 0; i < 4; i++) sacc[mf][nf][i] = 0.f;

#pragma unroll
                for (int ks = 0; ks < 8; ks++) {
                    const int kk = ks * 8 + 2 * tg;
                    uint32_t ah[2][4];
#pragma unroll
                    for (int mf = 0; mf < 2; mf++) {
                        const uint32_t* aph = Qh + (wrow + mf * 16 + gid) * QPAD + kk;
                        uint2 h0 = *(const uint2*)aph;
                        uint2 h1 = *(const uint2*)(aph + 8 * QPAD);
                        ah[mf][0] = h0.x; ah[mf][1] = h1.x;
                        ah[mf][2] = h0.y; ah[mf][3] = h1.y;
                    }
#pragma unroll
                    for (int nf = 0; nf < 8; nf++) {
                        uint2 bv = *(const uint2*)(Ks + (nf * 8 + gid) * QPAD + kk);
                        uint32_t bf[2] = {bv.x, bv.y};
                        mma_tf32(sacc[0][nf], ah[0], bf);
                        mma_tf32(sacc[1][nf], ah[1], bf);
                    }
                }

                // ---- causal mask ----
                if (kt >= 2 * qt) {
#pragma unroll
                    for (int mf = 0; mf < 2; mf++) {
                        const int r0g = q0 + wrow + mf * 16 + gid;
                        const int r1g = r0g + 8;
#pragma unroll
                        for (int nf = 0; nf < 8; nf++) {
                            const int cb = kt * 64 + nf * 8 + 2 * tg;
                            if (cb     > r0g) sacc[mf][nf][0] = -INFINITY;
                            if (cb + 1 > r0g) sacc[mf][nf][1] = -INFINITY;
                            if (cb     > r1g) sacc[mf][nf][2] = -INFINITY;
                            if (cb + 1 > r1g) sacc[mf][nf][3] = -INFINITY;
                        }
                    }
                }

                // ---- online softmax (exp2 domain), per m-frag ----
#pragma unroll
                for (int mf = 0; mf < 2; mf++) {
                    float mx0 = -INFINITY, mx1 = -INFINITY;
#pragma unroll
                    for (int nf = 0; nf < 8; nf++) {
                        mx0 = fmaxf(mx0, fmaxf(sacc[mf][nf][0], sacc[mf][nf][1]));
                        mx1 = fmaxf(mx1, fmaxf(sacc[mf][nf][2], sacc[mf][nf][3]));
                    }
                    mx0 = fmaxf(mx0, __shfl_xor_sync(0xffffffffu, mx0, 1));
                    mx0 = fmaxf(mx0, __shfl_xor_sync(0xffffffffu, mx0, 2));
                    mx1 = fmaxf(mx1, __shfl_xor_sync(0xffffffffu, mx1, 1));
                    mx1 = fmaxf(mx1, __shfl_xor_sync(0xffffffffu, mx1, 2));
                    const float mn0 = fmaxf(mv[2 * mf], mx0);
                    const float mn1 = fmaxf(mv[2 * mf + 1], mx1);
                    const float c0 = exp2f(mv[2 * mf] - mn0);
                    const float c1 = exp2f(mv[2 * mf + 1] - mn1);

                    float rs0 = 0.f, rs1 = 0.f;
#pragma unroll
                    for (int nf = 0; nf < 8; nf++) {
                        sacc[mf][nf][0] = exp2f(sacc[mf][nf][0] - mn0);
                        sacc[mf][nf][1] = exp2f(sacc[mf][nf][1] - mn0);
                        sacc[mf][nf][2] = exp2f(sacc[mf][nf][2] - mn1);
                        sacc[mf][nf][3] = exp2f(sacc[mf][nf][3] - mn1);
                        rs0 += sacc[mf][nf][0] + sacc[mf][nf][1];
                        rs1 += sacc[mf][nf][2] + sacc[mf][nf][3];
                    }
                    rs0 += __shfl_xor_sync(0xffffffffu, rs0, 1);
                    rs0 += __shfl_xor_sync(0xffffffffu, rs0, 2);
                    rs1 += __shfl_xor_sync(0xffffffffu, rs1, 1);
                    rs1 += __shfl_xor_sync(0xffffffffu, rs1, 2);
                    lv[2 * mf]     = lv[2 * mf] * c0 + rs0;
                    lv[2 * mf + 1] = lv[2 * mf + 1] * c1 + rs1;
                    mv[2 * mf] = mn0; mv[2 * mf + 1] = mn1;
#pragma unroll
                    for (int nf = 0; nf < 8; nf++) {
                        oacc[mf][nf][0] *= c0; oacc[mf][nf][1] *= c0;
                        oacc[mf][nf][2] *= c1; oacc[mf][nf][3] *= c1;
                    }
                }

                // ---- O += P V : V frags shared across 2 m-frags;
                //      S C-frag reused as A-frag (a = {c0,c2,c1,c3}) ----
#pragma unroll
                for (int ks = 0; ks < 8; ks++) {
                    uint32_t af[2][4];
#pragma unroll
                    for (int mf = 0; mf < 2; mf++) {
                        af[mf][0] = cvt_tf32(sacc[mf][ks][0]);
                        af[mf][1] = cvt_tf32(sacc[mf][ks][2]);
                        af[mf][2] = cvt_tf32(sacc[mf][ks][1]);
                        af[mf][3] = cvt_tf32(sacc[mf][ks][3]);
                    }
                    const int kk = ks * 8 + 2 * tg;
#pragma unroll
                    for (int nf = 0; nf < 8; nf++) {
                        uint2 bv = *(const uint2*)(Vs + (nf * 8 + gid) * VPAD + kk);
                        uint32_t bf[2] = {bv.x, bv.y};
                        mma_tf32(oacc[0][nf], af[0], bf);
                        mma_tf32(oacc[1][nf], af[1], bf);
                    }
                }
            }
            __syncthreads();
        }

        // ---- write O: natural-d cols -> kperm8 for gemm<1> layout ----
        float* Yg = g_y + ((size_t)bh * TT + q0) * DHH;
#pragma unroll
        for (int mf = 0; mf < 2; mf++) {
            const float i0 = 1.f / lv[2 * mf], i1 = 1.f / lv[2 * mf + 1];
            const int row0 = wrow + mf * 16 + gid;
#pragma unroll
            for (int nf = 0; nf < 8; nf++) {
                float* y0 = &Yg[row0 * DHH + nf * 8];
                float* y1 = &Yg[(row0 + 8) * DHH + nf * 8];
                y0[p0] = rnd_tf32(oacc[mf][nf][0] * i0);
                y0[p1] = rnd_tf32(oacc[mf][nf][1] * i0);
                y1[p0] = rnd_tf32(oacc[mf][nf][2] * i1);
                y1[p1] = rnd_tf32(oacc[mf][nf][3] * i1);
            }
        }
        __syncthreads();   // Q/K/V smem safe to reuse in next pass
    }
}

// ---------------------------------------------------------------------------
extern "C" void kernel_launch(void* const* d_in, const int* in_sizes, int n_in,
                              void* d_out, int out_size)
{
    (void)in_sizes; (void)n_in; (void)out_size;
    const float* x     = (const float*)d_in[0];
    const float* W_qkv = (const float*)d_in[2];
    const float* b_qkv = (const float*)d_in[3];
    const float* W_out = (const float*)d_in[4];
    const float* b_out = (const float*)d_in[5];
    float* out = (float*)d_out;

    cudaFuncSetAttribute(attn_mma,
                         cudaFuncAttributeMaxDynamicSharedMemorySize, ATTN_SMEM);
    cudaFuncSetAttribute(gemm_mma<0>,
                         cudaFuncAttributeMaxDynamicSharedMemorySize, GEMM_SMEM);
    cudaFuncSetAttribute(gemm_mma<1>,
                         cudaFuncAttributeMaxDynamicSharedMemorySize, GEMM_SMEM);

    float* wtq = nullptr; cudaGetSymbolAddress((void**)&wtq, g_wtq);
    float* wto = nullptr; cudaGetSymbolAddress((void**)&wto, g_wto);
    float* xr  = nullptr; cudaGetSymbolAddress((void**)&xr, g_xr);

    // 0) fused prep: rope table + rounded/permuted x + transposed weights
    prep_all<<<2048 + 3072 + 1024 + 256, 256>>>(x, W_qkv, W_out);

    // 1) QKV projection (V written transposed [b,h,d,t]; q natural)
    gemm_mma<0><<<dim3(3072 / 128, M_TOT / 128), 256, GEMM_SMEM>>>(xr, wtq, b_qkv, nullptr);

    // 2) RoPE on K only (q rope fused into attention)
    rope_k<<<(BB * HH * TT * 32) / 256, 256>>>();

    // 3) causal flash attention (paired q-tiles, 4 warps x 32 rows)
    attn_mma<<<dim3(8, BB * HH), 128, ATTN_SMEM>>>();

    // 4) output projection
    gemm_mma<1><<<dim3(DIMM / 128, M_TOT / 128), 256, GEMM_SMEM>>>(nullptr, wto, b_out, out);
}

// round 14
// speedup vs baseline: 1.0197x; 1.0197x over previous
#include <cuda_runtime.h>
#include <math.h>
#include <stdint.h>

#define BB 2
#define TT 2048
#define DIMM 1024
#define HH 16
#define DHH 64
#define M_TOT (BB*TT)        /* 4096 */

// Scratch (static device globals; allocation is forbidden)
__device__ float g_q[(size_t)BB*HH*TT*DHH];   // [b,h,t,d]   natural d (rope fused in attn)
__device__ float g_k[(size_t)BB*HH*TT*DHH];   // [b,h,t,d']  (d k-permuted by rope_k)
__device__ float g_v[(size_t)BB*HH*TT*DHH];   // [b,h,d,t]   TRANSPOSED, natural d
__device__ float g_y[(size_t)BB*HH*TT*DHH];   // [b,h,t,d']  (d k-permuted)
__device__ float g_xr[(size_t)M_TOT*DIMM];    // x rounded+k-permuted
__device__ float g_wtq[(size_t)3072*1024];    // W_qkv^T [n][k'] rounded+perm
__device__ float g_wto[(size_t)1024*1024];    // W_out^T [n][k'] rounded+perm
__device__ float g_rc[TT*32];                 // rope cos table
__device__ float g_rs[TT*32];                 // rope sin table

// 1/8 softmax scale folded with log2(e) for exp2-domain softmax
#define QSCALE 0.18033688068352986f

// k-permutation within 8-blocks: thread tg's pair (tg, tg+4) -> (2tg, 2tg+1)
__host__ __device__ __forceinline__ int kperm8(int j) {
    return ((j & 3) << 1) | (j >> 2);
}

// ---------------------------------------------------------------------------
// Helpers (legacy mma.sync tf32; tcgen05 needs the sm_103a feature target
// which this harness does not emit).
// ---------------------------------------------------------------------------
__device__ __forceinline__ uint32_t smem_u32(const void* p) {
    uint32_t a;
    asm("{ .reg .u64 t; cvta.to.shared.u64 t, %1; cvt.u32.u64 %0, t; }"
        : "=r"(a) : "l"(p));
    return a;
}
__device__ __forceinline__ uint32_t cvt_tf32(float f) {
    uint32_t u;
    asm("cvt.rna.tf32.f32 %0, %1;" : "=r"(u) : "f"(f));
    return u;
}
__device__ __forceinline__ float rnd_tf32(float f) {
    return __uint_as_float(cvt_tf32(f));
}
#define CP16(sa, gp) \
    asm volatile("cp.async.cg.shared.global [%0], [%1], 16;" :: "r"(sa), "l"(gp))
#define CP_COMMIT() asm volatile("cp.async.commit_group;" ::: "memory")
#define CP_WAIT1()  asm volatile("cp.async.wait_group 1;" ::: "memory")
#define CP_WAIT0()  asm volatile("cp.async.wait_group 0;" ::: "memory")

__device__ __forceinline__ void mma_tf32(float* c, const uint32_t* a,
                                         const uint32_t* b) {
    asm volatile(
        "mma.sync.aligned.m16n8k8.row.col.f32.tf32.tf32.f32 "
        "{%0,%1,%2,%3}, {%4,%5,%6,%7}, {%8,%9}, {%0,%1,%2,%3};"
        : "+f"(c[0]), "+f"(c[1]), "+f"(c[2]), "+f"(c[3])
        : "r"(a[0]), "r"(a[1]), "r"(a[2]), "r"(a[3]), "r"(b[0]), "r"(b[1]));
}

// ---------------------------------------------------------------------------
// Fused prep: round_x (2048 blocks) | transpose W_qkv (3072) |
// transpose W_out (1024) | build_rope (256). All independent.
// ---------------------------------------------------------------------------
__global__ void prep_all(const float* __restrict__ x,
                         const float* __restrict__ Wq,
                         const float* __restrict__ Wo)
{
    __shared__ float t[32][33];
    const int b = blockIdx.x;
    const int tid = threadIdx.x;

    if (b < 2048) {                      // ---- round_x + k-permute ----
        const int i = b * 256 + tid;
        float4 a = ((const float4*)x)[2 * i];
        float4 c = ((const float4*)x)[2 * i + 1];
        float4 o0 = make_float4(rnd_tf32(a.x), rnd_tf32(c.x), rnd_tf32(a.y), rnd_tf32(c.y));
        float4 o1 = make_float4(rnd_tf32(a.z), rnd_tf32(c.z), rnd_tf32(a.w), rnd_tf32(c.w));
        ((float4*)g_xr)[2 * i] = o0;
        ((float4*)g_xr)[2 * i + 1] = o1;
    } else if (b < 2048 + 3072 + 1024) { // ---- weight transpose+round+perm ----
        const float* src;
        float* dst;
        int C, c0, r0;
        if (b < 2048 + 3072) {
            const int bb = b - 2048;
            src = Wq; dst = g_wtq; C = 3072;
            c0 = (bb % 96) * 32; r0 = (bb / 96) * 32;
        } else {
            const int bb = b - 2048 - 3072;
            src = Wo; dst = g_wto; C = 1024;
            c0 = (bb % 32) * 32; r0 = (bb / 32) * 32;
        }
        const int tx = tid & 31, ty = tid >> 5;
        for (int i = ty; i < 32; i += 8)
            t[i][tx] = src[(size_t)(r0 + i) * C + c0 + tx];
        __syncthreads();
        const int kp = (tx & 24) | kperm8(tx & 7);
        for (int i = ty; i < 32; i += 8)
            dst[(size_t)(c0 + i) * 1024 + r0 + kp] = rnd_tf32(t[tx][i]);
    } else {                             // ---- build rope table (fp64) ----
        const int idx = (b - 6144) * 256 + tid;
        const int d = idx & 31, tt = idx >> 5;
        const float invf = (float)exp(-(double)d * (log(10000.0) / 32.0));
        const float ang = (float)tt * invf;
        double sd, cd;
        sincos((double)ang, &sd, &cd);
        g_rc[tt * 32 + d] = (float)cd;
        g_rs[tt * 32 + d] = (float)sd;
    }
}

// ---------------------------------------------------------------------------
// mma.sync tf32 GEMM, CTA 128x128, BK=32, 8 warps, warp 64x32.
// XOR-swizzled SMEM, 3-stage cp.async pipeline, SINGLE barrier per chunk
// (canonical multistage order: wait -> bar -> issue c+2 -> compute c).
// ---------------------------------------------------------------------------
#define ATILE 16384                       /* 128*32*4 bytes */
#define STAGE (2 * ATILE)                 /* A + B */
#define GEMM_SMEM (3 * STAGE)             /* 98304 */

template <int MODE>
__global__ __launch_bounds__(256) void gemm_mma(
    const float* __restrict__ A, const float* __restrict__ Bt,
    const float* __restrict__ bias, float* __restrict__ out)
{
    extern __shared__ char smem[];
    const uint32_t sb = smem_u32(smem);
    const int tid = threadIdx.x;
    const int wid = tid >> 5;
    const int lane = tid & 31;
    const int gid = lane >> 2;
    const int tg = lane & 3;
    const int mb = (wid >> 2) * 64;
    const int nb = (wid & 3) * 32;
    const int m0 = blockIdx.y * 128;
    const int n0 = blockIdx.x * 128;
    const int sg = gid & 3;               // swizzle group selector

    float acc[4][4][4];
#pragma unroll
    for (int mf = 0; mf < 4; mf++)
#pragma unroll
        for (int nf = 0; nf < 4; nf++)
#pragma unroll
            for (int i = 0; i < 4; i++) acc[mf][nf][i] = 0.f;

    auto issue_tile = [&](int c) {
        const int p = c % 3;
        const int k0 = c * 32;
        const uint32_t aBase = sb + p * STAGE;
        const uint32_t bBase = aBase + ATILE;
#pragma unroll
        for (int i = 0; i < 4; i++) {
            const int e = tid + 256 * i;
            const int rr = e >> 3, q = e & 7;
            const uint32_t w = (uint32_t)(rr * 32 + (((q >> 1) ^ (rr & 3)) << 3)
                                          + (q & 1) * 4);
            const float* gp;
            if (MODE == 0) {
                gp = &A[(size_t)(m0 + rr) * 1024 + k0 + q * 4];
            } else {
                const int m = m0 + rr, b = m >> 11, t = m & (TT - 1);
                const int kk = k0 + q * 4, h = kk >> 6, d = kk & 63;
                gp = &g_y[(((size_t)b * HH + h) * TT + t) * DHH + d];
            }
            CP16(aBase + w * 4, gp);
        }
#pragma unroll
        for (int i = 0; i < 4; i++) {
            const int e = tid + 256 * i;
            const int rr = e >> 3, q = e & 7;
            const uint32_t w = (uint32_t)(rr * 32 + (((q >> 1) ^ (rr & 3)) << 3)
                                          + (q & 1) * 4);
            const float* gp = &Bt[(size_t)(n0 + rr) * 1024 + k0 + q * 4];
            CP16(bBase + w * 4, gp);
        }
        CP_COMMIT();
    };

    issue_tile(0);
    issue_tile(1);
    for (int c = 0; c < 32; c++) {
        if (c + 1 < 32) CP_WAIT1();      // group c complete
        else            CP_WAIT0();
        __syncthreads();                 // stage-c visible; stage (c-1)%3 free
        if (c + 2 < 32) issue_tile(c + 2);

        const int p = c % 3;
        const uint32_t* As = (const uint32_t*)(smem + p * STAGE);
        const uint32_t* Bs = (const uint32_t*)(smem + p * STAGE + ATILE);
#pragma unroll
        for (int ks = 0; ks < 4; ks++) {
            const int xo = ((ks ^ sg) << 3) + 2 * tg;
            uint32_t af[4][4], bf[4][2];
#pragma unroll
            for (int mf = 0; mf < 4; mf++) {
                const uint32_t* ap = As + (mb + mf * 16 + gid) * 32 + xo;
                uint2 lo = *(const uint2*)ap;
                uint2 hi = *(const uint2*)(ap + 256);
                af[mf][0] = lo.x; af[mf][2] = lo.y;
                af[mf][1] = hi.x; af[mf][3] = hi.y;
            }
#pragma unroll
            for (int nf = 0; nf < 4; nf++) {
                const uint32_t* bp = Bs + (nb + nf * 8 + gid) * 32 + xo;
                uint2 v = *(const uint2*)bp;
                bf[nf][0] = v.x; bf[nf][1] = v.y;
            }
#pragma unroll
            for (int mf = 0; mf < 4; mf++)
#pragma unroll
                for (int nf = 0; nf < 4; nf++)
                    mma_tf32(acc[mf][nf], af[mf], bf[nf]);
        }
    }

#pragma unroll
    for (int mf = 0; mf < 4; mf++) {
        const int r0 = m0 + mb + mf * 16 + gid;
#pragma unroll
        for (int nf = 0; nf < 4; nf++) {
            const int n = n0 + nb + nf * 8 + tg * 2;
            const float bx = bias[n], by = bias[n + 1];
            float2 v0 = make_float2(acc[mf][nf][0] + bx, acc[mf][nf][1] + by);
            float2 v1 = make_float2(acc[mf][nf][2] + bx, acc[mf][nf][3] + by);
            if (MODE == 0) {
                const int which = n >> 10;
                const int rr = n & 1023;
                const int h = rr >> 6, d = rr & 63;
                const int b0i = r0 >> 11, t0i = r0 & (TT - 1);
                const int m1 = r0 + 8;
                const int b1i = m1 >> 11, t1i = m1 & (TT - 1);
                if (which == 2) {
                    const size_t vb0 = ((size_t)b0i * HH + h) * DHH;
                    const size_t vb1 = ((size_t)b1i * HH + h) * DHH;
                    g_v[(vb0 + d    ) * TT + t0i] = rnd_tf32(v0.x);
                    g_v[(vb0 + d + 1) * TT + t0i] = rnd_tf32(v0.y);
                    g_v[(vb1 + d    ) * TT + t1i] = rnd_tf32(v1.x);
                    g_v[(vb1 + d + 1) * TT + t1i] = rnd_tf32(v1.y);
                } else {
                    float* dst = (which == 0) ? g_q : g_k;
                    *(float2*)&dst[(((size_t)b0i * HH + h) * TT + t0i) * DHH + d] = v0;
                    *(float2*)&dst[(((size_t)b1i * HH + h) * TT + t1i) * DHH + d] = v1;
                }
            } else {
                *(float2*)&out[(size_t)r0 * DIMM + n] = v0;
                *(float2*)&out[(size_t)(r0 + 8) * DIMM + n] = v1;
            }
        }
    }
}

// ---------------------------------------------------------------------------
// RoPE on K only (q rope fused into attention).
// ---------------------------------------------------------------------------
__global__ void rope_k()
{
    const int idx = blockIdx.x * blockDim.x + threadIdx.x;   // 2^21
    const int d  = idx & 31;
    const int t  = (idx >> 5) & (TT - 1);
    const int bh = idx >> 16;
    const float cf = g_rc[t * 32 + d];
    const float sf = g_rs[t * 32 + d];
    const int dp = (d & 24) | kperm8(d & 7);

    const size_t base = ((size_t)bh * TT + t) * DHH;
    const float ka = g_k[base + d], kb = g_k[base + 32 + d];
    g_k[base + dp]      = rnd_tf32(ka * cf - kb * sf);
    g_k[base + 32 + dp] = rnd_tf32(ka * sf + kb * cf);
}

// ---------------------------------------------------------------------------
// Flash attention (exact R12 version, the proven best): 8 warps x 16 rows,
// 256 threads, paired q-tiles (one wave), fused Q-rope, exp2 softmax,
// S C-frag reused as PV A-frag, transposed V.
// ---------------------------------------------------------------------------
#define QPAD 72
#define VPAD 72
#define OFF_QH 0
#define OFF_KS (128*QPAD)
#define OFF_VS (OFF_KS + 2*64*QPAD)
#define ATTN_SMEM ((OFF_VS + 2*64*VPAD) * 4)   /* 110592 */

__global__ __launch_bounds__(256, 2) void attn_mma()
{
    extern __shared__ float sm[];
    uint32_t* Qh = (uint32_t*)sm + OFF_QH;
    const uint32_t sb = smem_u32(sm);

    const int bh = blockIdx.y;
    const int tid = threadIdx.x;
    const int wid = tid >> 5;
    const int lane = tid & 31;
    const int gid = lane >> 2;
    const int tg = lane & 3;
    const int wrow = wid * 16;

    const float* Kg = g_k + (size_t)bh * TT * DHH;
    const float* Vg = g_v + (size_t)bh * DHH * TT;   // [d][t]

    const int p0 = kperm8(2 * tg), p1 = kperm8(2 * tg + 1);

#pragma unroll 1
    for (int pass = 0; pass < 2; pass++) {
        const int qt = pass == 0 ? (15 - (int)blockIdx.x) : (int)blockIdx.x;
        const int q0 = qt * 128;
        const float* Qg = g_q + ((size_t)bh * TT + q0) * DHH;

        // Load Q natural, fused RoPE (table), scale, cvt, store d-permuted
#pragma unroll
        for (int i = 0; i < 4; i++) {
            const int e = tid + 256 * i;        // 0..1023
            const int r = e >> 3, j = e & 7;
            const int d0 = j * 4;
            const int t = q0 + r;
            float4 qa = *(const float4*)&Qg[r * DHH + d0];
            float4 qb = *(const float4*)&Qg[r * DHH + 32 + d0];
            float4 cs = *(const float4*)&g_rc[t * 32 + d0];
            float4 sn = *(const float4*)&g_rs[t * 32 + d0];
            float lo[4] = {qa.x * cs.x - qb.x * sn.x, qa.y * cs.y - qb.y * sn.y,
                           qa.z * cs.z - qb.z * sn.z, qa.w * cs.w - qb.w * sn.w};
            float hi[4] = {qa.x * sn.x + qb.x * cs.x, qa.y * sn.y + qb.y * cs.y,
                           qa.z * sn.z + qb.z * cs.z, qa.w * sn.w + qb.w * cs.w};
#pragma unroll
            for (int u = 0; u < 4; u++) {
                const int dd = d0 + u;
                const int dp = (dd & 24) | kperm8(dd & 7);
                Qh[r * QPAD + dp]      = cvt_tf32(lo[u] * QSCALE);
                Qh[r * QPAD + 32 + dp] = cvt_tf32(hi[u] * QSCALE);
            }
        }

        float oacc[8][4];
#pragma unroll
        for (int nf = 0; nf < 8; nf++)
#pragma unroll
            for (int i = 0; i < 4; i++) oacc[nf][i] = 0.f;
        float m0v = -INFINITY, m1v = -INFINITY, l0 = 0.f, l1 = 0.f;

        const int r0g = q0 + wrow + gid;
        const int r1g = r0g + 8;
        const int nkt = 2 * qt + 2;

        auto issue = [&](int kt) {
            const int st = kt & 1;
            const uint32_t kb = sb + (OFF_KS + st * 64 * QPAD) * 4;
            const uint32_t vb = sb + (OFF_VS + st * 64 * VPAD) * 4;
#pragma unroll
            for (int i = 0; i < 4; i++) {
                const int e = tid + 256 * i;
                const int r = e >> 4, c = (e & 15) * 4;
                CP16(kb + (uint32_t)(r * QPAD + c) * 4,
                     &Kg[(size_t)(kt * 64 + r) * DHH + c]);
                CP16(vb + (uint32_t)(r * VPAD + c) * 4,
                     &Vg[(size_t)r * TT + kt * 64 + c]);
            }
            CP_COMMIT();
        };

        issue(0);
        for (int kt = 0; kt < nkt; kt++) {
            if (kt + 1 < nkt) { issue(kt + 1); CP_WAIT1(); }
            else              { CP_WAIT0(); }
            __syncthreads();

            if (kt * 64 <= q0 + wrow + 15) {
                const int st = kt & 1;
                const uint32_t* Ks = (const uint32_t*)sm + OFF_KS + st * 64 * QPAD;
                const uint32_t* Vs = (const uint32_t*)sm + OFF_VS + st * 64 * VPAD;

                // ---- S = Q K^T (single tf32, log2-scaled), paired LDS.64 ----
                float sacc[8][4];
#pragma unroll
                for (int nf = 0; nf < 8; nf++)
#pragma unroll
                    for (int i = 0; i < 4; i++) sacc[nf][i] = 0.f;

#pragma unroll
                for (int ks = 0; ks < 8; ks++) {
                    const int kk = ks * 8 + 2 * tg;
                    const uint32_t* aph = Qh + (wrow + gid) * QPAD + kk;
                    uint2 h0 = *(const uint2*)aph;
                    uint2 h1 = *(const uint2*)(aph + 8 * QPAD);
                    uint32_t ah[4] = {h0.x, h1.x, h0.y, h1.y};
#pragma unroll
                    for (int nf = 0; nf < 8; nf++) {
                        uint2 bv = *(const uint2*)(Ks + (nf * 8 + gid) * QPAD + kk);
                        uint32_t bf[2] = {bv.x, bv.y};
                        mma_tf32(sacc[nf], ah, bf);
                    }
                }

                // ---- causal mask ----
                if (kt >= 2 * qt) {
#pragma unroll
                    for (int nf = 0; nf < 8; nf++) {
                        const int cb = kt * 64 + nf * 8 + 2 * tg;
                        if (cb     > r0g) sacc[nf][0] = -INFINITY;
                        if (cb + 1 > r0g) sacc[nf][1] = -INFINITY;
                        if (cb     > r1g) sacc[nf][2] = -INFINITY;
                        if (cb + 1 > r1g) sacc[nf][3] = -INFINITY;
                    }
                }

                // ---- online softmax (exp2 domain) ----
                float mx0 = -INFINITY, mx1 = -INFINITY;
#pragma unroll
                for (int nf = 0; nf < 8; nf++) {
                    mx0 = fmaxf(mx0, fmaxf(sacc[nf][0], sacc[nf][1]));
                    mx1 = fmaxf(mx1, fmaxf(sacc[nf][2], sacc[nf][3]));
                }
                mx0 = fmaxf(mx0, __shfl_xor_sync(0xffffffffu, mx0, 1));
                mx0 = fmaxf(mx0, __shfl_xor_sync(0xffffffffu, mx0, 2));
                mx1 = fmaxf(mx1, __shfl_xor_sync(0xffffffffu, mx1, 1));
                mx1 = fmaxf(mx1, __shfl_xor_sync(0xffffffffu, mx1, 2));
                const float mn0 = fmaxf(m0v, mx0), mn1 = fmaxf(m1v, mx1);
                const float c0 = exp2f(m0v - mn0), c1 = exp2f(m1v - mn1);

                float rs0 = 0.f, rs1 = 0.f;
#pragma unroll
                for (int nf = 0; nf < 8; nf++) {
                    sacc[nf][0] = exp2f(sacc[nf][0] - mn0);
                    sacc[nf][1] = exp2f(sacc[nf][1] - mn0);
                    sacc[nf][2] = exp2f(sacc[nf][2] - mn1);
                    sacc[nf][3] = exp2f(sacc[nf][3] - mn1);
                    rs0 += sacc[nf][0] + sacc[nf][1];
                    rs1 += sacc[nf][2] + sacc[nf][3];
                }
                rs0 += __shfl_xor_sync(0xffffffffu, rs0, 1);
                rs0 += __shfl_xor_sync(0xffffffffu, rs0, 2);
                rs1 += __shfl_xor_sync(0xffffffffu, rs1, 1);
                rs1 += __shfl_xor_sync(0xffffffffu, rs1, 2);
                l0 = l0 * c0 + rs0;
                l1 = l1 * c1 + rs1;
                m0v = mn0; m1v = mn1;
#pragma unroll
                for (int nf = 0; nf < 8; nf++) {
                    oacc[nf][0] *= c0; oacc[nf][1] *= c0;
                    oacc[nf][2] *= c1; oacc[nf][3] *= c1;
                }

                // ---- O += P V : C-frag reused as A-frag (a={c0,c2,c1,c3});
                //      effective key order (2tg,2tg+1) = Vt natural cols ----
#pragma unroll
                for (int ks = 0; ks < 8; ks++) {
                    uint32_t af[4] = {cvt_tf32(sacc[ks][0]), cvt_tf32(sacc[ks][2]),
                                      cvt_tf32(sacc[ks][1]), cvt_tf32(sacc[ks][3])};
                    const int kk = ks * 8 + 2 * tg;
#pragma unroll
                    for (int nf = 0; nf < 8; nf++) {
                        uint2 bv = *(const uint2*)(Vs + (nf * 8 + gid) * VPAD + kk);
                        uint32_t bf[2] = {bv.x, bv.y};
                        mma_tf32(oacc[nf], af, bf);
                    }
                }
            }
            __syncthreads();
        }

        // ---- write O: natural-d cols -> kperm8 for gemm<1> layout ----
        const float i0 = 1.f / l0, i1 = 1.f / l1;
        float* Yg = g_y + ((size_t)bh * TT + q0) * DHH;
#pragma unroll
        for (int nf = 0; nf < 8; nf++) {
            float* y0 = &Yg[(wrow + gid) * DHH + nf * 8];
            float* y1 = &Yg[(wrow + gid + 8) * DHH + nf * 8];
            y0[p0] = rnd_tf32(oacc[nf][0] * i0);
            y0[p1] = rnd_tf32(oacc[nf][1] * i0);
            y1[p0] = rnd_tf32(oacc[nf][2] * i1);
            y1[p1] = rnd_tf32(oacc[nf][3] * i1);
        }
        __syncthreads();   // Q/K/V smem safe to reuse in next pass
    }
}

// ---------------------------------------------------------------------------
extern "C" void kernel_launch(void* const* d_in, const int* in_sizes, int n_in,
                              void* d_out, int out_size)
{
    (void)in_sizes; (void)n_in; (void)out_size;
    const float* x     = (const float*)d_in[0];
    const float* W_qkv = (const float*)d_in[2];
    const float* b_qkv = (const float*)d_in[3];
    const float* W_out = (const float*)d_in[4];
    const float* b_out = (const float*)d_in[5];
    float* out = (float*)d_out;

    cudaFuncSetAttribute(attn_mma,
                         cudaFuncAttributeMaxDynamicSharedMemorySize, ATTN_SMEM);
    cudaFuncSetAttribute(gemm_mma<0>,
                         cudaFuncAttributeMaxDynamicSharedMemorySize, GEMM_SMEM);
    cudaFuncSetAttribute(gemm_mma<1>,
                         cudaFuncAttributeMaxDynamicSharedMemorySize, GEMM_SMEM);

    float* wtq = nullptr; cudaGetSymbolAddress((void**)&wtq, g_wtq);
    float* wto = nullptr; cudaGetSymbolAddress((void**)&wto, g_wto);
    float* xr  = nullptr; cudaGetSymbolAddress((void**)&xr, g_xr);

    // 0) fused prep: rope table + rounded/permuted x + transposed weights
    prep_all<<<2048 + 3072 + 1024 + 256, 256>>>(x, W_qkv, W_out);

    // 1) QKV projection (V written transposed [b,h,d,t]; q natural)
    gemm_mma<0><<<dim3(3072 / 128, M_TOT / 128), 256, GEMM_SMEM>>>(xr, wtq, b_qkv, nullptr);

    // 2) RoPE on K only (q rope fused into attention)
    rope_k<<<(BB * HH * TT * 32) / 256, 256>>>();

    // 3) causal flash attention (paired q-tiles, one wave)
    attn_mma<<<dim3(8, BB * HH), 256, ATTN_SMEM>>>();

    // 4) output projection
    gemm_mma<1><<<dim3(DIMM / 128, M_TOT / 128), 256, GEMM_SMEM>>>(nullptr, wto, b_out, out);
}

// round 15
// speedup vs baseline: 1.0252x; 1.0054x over previous
#include <cuda_runtime.h>
#include <math.h>
#include <stdint.h>

#define BB 2
#define TT 2048
#define DIMM 1024
#define HH 16
#define DHH 64
#define M_TOT (BB*TT)        /* 4096 */

// Scratch (static device globals; allocation is forbidden)
__device__ float g_q[(size_t)BB*HH*TT*DHH];   // [b,h,t,d]   natural d (rope fused in attn)
__device__ float g_k[(size_t)BB*HH*TT*DHH];   // [b,h,t,d']  rope'd+permuted (fused in gemm<0>)
__device__ float g_v[(size_t)BB*HH*TT*DHH];   // [b,h,d,t]   TRANSPOSED, natural d
__device__ float g_y[(size_t)BB*HH*TT*DHH];   // [b,h,t,d']  (d k-permuted)
__device__ float g_xr[(size_t)M_TOT*DIMM];    // x rounded+k-permuted
__device__ float g_wtq[(size_t)3072*1024];    // W_qkv^T [n][k'] rounded+perm
__device__ float g_wto[(size_t)1024*1024];    // W_out^T [n][k'] rounded+perm
__device__ float g_rc[TT*32];                 // rope cos table
__device__ float g_rs[TT*32];                 // rope sin table

// 1/8 softmax scale folded with log2(e) for exp2-domain softmax
#define QSCALE 0.18033688068352986f

// k-permutation within 8-blocks: thread tg's pair (tg, tg+4) -> (2tg, 2tg+1)
__host__ __device__ __forceinline__ int kperm8(int j) {
    return ((j & 3) << 1) | (j >> 2);
}

// ---------------------------------------------------------------------------
// Helpers (legacy mma.sync tf32; tcgen05 needs the sm_103a feature target
// which this harness does not emit).
// ---------------------------------------------------------------------------
__device__ __forceinline__ uint32_t smem_u32(const void* p) {
    uint32_t a;
    asm("{ .reg .u64 t; cvta.to.shared.u64 t, %1; cvt.u32.u64 %0, t; }"
        : "=r"(a) : "l"(p));
    return a;
}
__device__ __forceinline__ uint32_t cvt_tf32(float f) {
    uint32_t u;
    asm("cvt.rna.tf32.f32 %0, %1;" : "=r"(u) : "f"(f));
    return u;
}
__device__ __forceinline__ float rnd_tf32(float f) {
    return __uint_as_float(cvt_tf32(f));
}
#define CP16(sa, gp) \
    asm volatile("cp.async.cg.shared.global [%0], [%1], 16;" :: "r"(sa), "l"(gp))
#define CP_COMMIT() asm volatile("cp.async.commit_group;" ::: "memory")
#define CP_WAIT1()  asm volatile("cp.async.wait_group 1;" ::: "memory")
#define CP_WAIT0()  asm volatile("cp.async.wait_group 0;" ::: "memory")

__device__ __forceinline__ void mma_tf32(float* c, const uint32_t* a,
                                         const uint32_t* b) {
    asm volatile(
        "mma.sync.aligned.m16n8k8.row.col.f32.tf32.tf32.f32 "
        "{%0,%1,%2,%3}, {%4,%5,%6,%7}, {%8,%9}, {%0,%1,%2,%3};"
        : "+f"(c[0]), "+f"(c[1]), "+f"(c[2]), "+f"(c[3])
        : "r"(a[0]), "r"(a[1]), "r"(a[2]), "r"(a[3]), "r"(b[0]), "r"(b[1]));
}

// ---------------------------------------------------------------------------
// Fused prep: round_x (2048 blocks) | transpose W_qkv (3072) |
// transpose W_out (1024) | build_rope (256). All independent.
// ---------------------------------------------------------------------------
__global__ void prep_all(const float* __restrict__ x,
                         const float* __restrict__ Wq,
                         const float* __restrict__ Wo)
{
    __shared__ float t[32][33];
    const int b = blockIdx.x;
    const int tid = threadIdx.x;

    if (b < 2048) {                      // ---- round_x + k-permute ----
        const int i = b * 256 + tid;
        float4 a = ((const float4*)x)[2 * i];
        float4 c = ((const float4*)x)[2 * i + 1];
        float4 o0 = make_float4(rnd_tf32(a.x), rnd_tf32(c.x), rnd_tf32(a.y), rnd_tf32(c.y));
        float4 o1 = make_float4(rnd_tf32(a.z), rnd_tf32(c.z), rnd_tf32(a.w), rnd_tf32(c.w));
        ((float4*)g_xr)[2 * i] = o0;
        ((float4*)g_xr)[2 * i + 1] = o1;
    } else if (b < 2048 + 3072 + 1024) { // ---- weight transpose+round+perm ----
        const float* src;
        float* dst;
        int C, c0, r0;
        if (b < 2048 + 3072) {
            const int bb = b - 2048;
            src = Wq; dst = g_wtq; C = 3072;
            c0 = (bb % 96) * 32; r0 = (bb / 96) * 32;
        } else {
            const int bb = b - 2048 - 3072;
            src = Wo; dst = g_wto; C = 1024;
            c0 = (bb % 32) * 32; r0 = (bb / 32) * 32;
        }
        const int tx = tid & 31, ty = tid >> 5;
        for (int i = ty; i < 32; i += 8)
            t[i][tx] = src[(size_t)(r0 + i) * C + c0 + tx];
        __syncthreads();
        const int kp = (tx & 24) | kperm8(tx & 7);
        for (int i = ty; i < 32; i += 8)
            dst[(size_t)(c0 + i) * 1024 + r0 + kp] = rnd_tf32(t[tx][i]);
    } else {                             // ---- build rope table (fp64) ----
        const int idx = (b - 6144) * 256 + tid;
        const int d = idx & 31, tt = idx >> 5;
        const float invf = (float)exp(-(double)d * (log(10000.0) / 32.0));
        const float ang = (float)tt * invf;
        double sd, cd;
        sincos((double)ang, &sd, &cd);
        g_rc[tt * 32 + d] = (float)cd;
        g_rs[tt * 32 + d] = (float)sd;
    }
}

// ---------------------------------------------------------------------------
// mma.sync tf32 GEMM, CTA 128x128, BK=32, 8 warps, warp 64x32.
// XOR-swizzled SMEM, 3-stage cp.async pipeline, single barrier per chunk.
// MODE 0 K-columns: rope fused in epilogue (smem pair-exchange, table rope,
// rounded+permuted store) -- replaces the separate rope_k kernel.
// ---------------------------------------------------------------------------
#define ATILE 16384                       /* 128*32*4 bytes */
#define STAGE (2 * ATILE)                 /* A + B */
#define GEMM_SMEM (3 * STAGE)             /* 98304 */

template <int MODE>
__global__ __launch_bounds__(256) void gemm_mma(
    const float* __restrict__ A, const float* __restrict__ Bt,
    const float* __restrict__ bias, float* __restrict__ out)
{
    extern __shared__ char smem[];
    const uint32_t sb = smem_u32(smem);
    const int tid = threadIdx.x;
    const int wid = tid >> 5;
    const int lane = tid & 31;
    const int gid = lane >> 2;
    const int tg = lane & 3;
    const int mb = (wid >> 2) * 64;
    const int nb = (wid & 3) * 32;
    const int m0 = blockIdx.y * 128;
    const int n0 = blockIdx.x * 128;
    const int sg = gid & 3;               // swizzle group selector

    float acc[4][4][4];
#pragma unroll
    for (int mf = 0; mf < 4; mf++)
#pragma unroll
        for (int nf = 0; nf < 4; nf++)
#pragma unroll
            for (int i = 0; i < 4; i++) acc[mf][nf][i] = 0.f;

    auto issue_tile = [&](int c) {
        const int p = c % 3;
        const int k0 = c * 32;
        const uint32_t aBase = sb + p * STAGE;
        const uint32_t bBase = aBase + ATILE;
#pragma unroll
        for (int i = 0; i < 4; i++) {
            const int e = tid + 256 * i;
            const int rr = e >> 3, q = e & 7;
            const uint32_t w = (uint32_t)(rr * 32 + (((q >> 1) ^ (rr & 3)) << 3)
                                          + (q & 1) * 4);
            const float* gp;
            if (MODE == 0) {
                gp = &A[(size_t)(m0 + rr) * 1024 + k0 + q * 4];
            } else {
                const int m = m0 + rr, b = m >> 11, t = m & (TT - 1);
                const int kk = k0 + q * 4, h = kk >> 6, d = kk & 63;
                gp = &g_y[(((size_t)b * HH + h) * TT + t) * DHH + d];
            }
            CP16(aBase + w * 4, gp);
        }
#pragma unroll
        for (int i = 0; i < 4; i++) {
            const int e = tid + 256 * i;
            const int rr = e >> 3, q = e & 7;
            const uint32_t w = (uint32_t)(rr * 32 + (((q >> 1) ^ (rr & 3)) << 3)
                                          + (q & 1) * 4);
            const float* gp = &Bt[(size_t)(n0 + rr) * 1024 + k0 + q * 4];
            CP16(bBase + w * 4, gp);
        }
        CP_COMMIT();
    };

    issue_tile(0);
    issue_tile(1);
    for (int c = 0; c < 32; c++) {
        if (c + 1 < 32) CP_WAIT1();
        else            CP_WAIT0();
        __syncthreads();
        if (c + 2 < 32) issue_tile(c + 2);

        const int p = c % 3;
        const uint32_t* As = (const uint32_t*)(smem + p * STAGE);
        const uint32_t* Bs = (const uint32_t*)(smem + p * STAGE + ATILE);
#pragma unroll
        for (int ks = 0; ks < 4; ks++) {
            const int xo = ((ks ^ sg) << 3) + 2 * tg;
            uint32_t af[4][4], bf[4][2];
#pragma unroll
            for (int mf = 0; mf < 4; mf++) {
                const uint32_t* ap = As + (mb + mf * 16 + gid) * 32 + xo;
                uint2 lo = *(const uint2*)ap;
                uint2 hi = *(const uint2*)(ap + 256);
                af[mf][0] = lo.x; af[mf][2] = lo.y;
                af[mf][1] = hi.x; af[mf][3] = hi.y;
            }
#pragma unroll
            for (int nf = 0; nf < 4; nf++) {
                const uint32_t* bp = Bs + (nb + nf * 8 + gid) * 32 + xo;
                uint2 v = *(const uint2*)bp;
                bf[nf][0] = v.x; bf[nf][1] = v.y;
            }
#pragma unroll
            for (int mf = 0; mf < 4; mf++)
#pragma unroll
                for (int nf = 0; nf < 4; nf++)
                    mma_tf32(acc[mf][nf], af[mf], bf[nf]);
        }
    }

    const int which = (MODE == 0) ? (n0 >> 10) : -1;   // constant per CTA

    if (MODE == 0 && which == 1) {
        // ---- K path: stage -> barrier -> fused rope -> g_k (rounded+perm)
        float* stg = (float*)smem;        // [128][132] = 67.6 KB
        __syncthreads();                  // pipeline smem dead
#pragma unroll
        for (int mf = 0; mf < 4; mf++) {
            const int r0 = mb + mf * 16 + gid;
#pragma unroll
            for (int nf = 0; nf < 4; nf++) {
                const int cc = nb + nf * 8 + tg * 2;
                const int n = n0 + cc;
                const float bx = bias[n], by = bias[n + 1];
                stg[r0 * 132 + cc]           = acc[mf][nf][0] + bx;
                stg[r0 * 132 + cc + 1]       = acc[mf][nf][1] + by;
                stg[(r0 + 8) * 132 + cc]     = acc[mf][nf][2] + bx;
                stg[(r0 + 8) * 132 + cc + 1] = acc[mf][nf][3] + by;
            }
        }
        __syncthreads();
        if (!(nb & 32)) {                 // low-half warps write both halves
#pragma unroll
            for (int mf = 0; mf < 4; mf++) {
#pragma unroll
                for (int half = 0; half < 2; half++) {
                    const int row = mb + mf * 16 + gid + half * 8;
                    const int m = m0 + row;
                    const int b = m >> 11, t = m & (TT - 1);
#pragma unroll
                    for (int nf = 0; nf < 4; nf++) {
#pragma unroll
                        for (int e = 0; e < 2; e++) {
                            const int cc = nb + nf * 8 + tg * 2 + e;  // d<32
                            const int d = cc & 63;
                            const float lo = stg[row * 132 + cc];
                            const float hv = stg[row * 132 + (cc ^ 32)];
                            const float cf = g_rc[t * 32 + d];
                            const float sf = g_rs[t * 32 + d];
                            const int h = ((n0 + cc) - 1024) >> 6;
                            const int dp = (d & 24) | kperm8(d & 7);
                            float* kb = &g_k[(((size_t)b * HH + h) * TT + t) * DHH];
                            kb[dp]      = rnd_tf32(lo * cf - hv * sf);
                            kb[32 + dp] = rnd_tf32(lo * sf + hv * cf);
                        }
                    }
                }
            }
        }
        return;
    }

#pragma unroll
    for (int mf = 0; mf < 4; mf++) {
        const int r0 = m0 + mb + mf * 16 + gid;
#pragma unroll
        for (int nf = 0; nf < 4; nf++) {
            const int n = n0 + nb + nf * 8 + tg * 2;
            const float bx = bias[n], by = bias[n + 1];
            float2 v0 = make_float2(acc[mf][nf][0] + bx, acc[mf][nf][1] + by);
            float2 v1 = make_float2(acc[mf][nf][2] + bx, acc[mf][nf][3] + by);
            if (MODE == 0) {
                const int rr = n & 1023;
                const int h = rr >> 6, d = rr & 63;
                const int b0i = r0 >> 11, t0i = r0 & (TT - 1);
                const int m1 = r0 + 8;
                const int b1i = m1 >> 11, t1i = m1 & (TT - 1);
                if (which == 2) {
                    const size_t vb0 = ((size_t)b0i * HH + h) * DHH;
                    const size_t vb1 = ((size_t)b1i * HH + h) * DHH;
                    g_v[(vb0 + d    ) * TT + t0i] = rnd_tf32(v0.x);
                    g_v[(vb0 + d + 1) * TT + t0i] = rnd_tf32(v0.y);
                    g_v[(vb1 + d    ) * TT + t1i] = rnd_tf32(v1.x);
                    g_v[(vb1 + d + 1) * TT + t1i] = rnd_tf32(v1.y);
                } else {
                    *(float2*)&g_q[(((size_t)b0i * HH + h) * TT + t0i) * DHH + d] = v0;
                    *(float2*)&g_q[(((size_t)b1i * HH + h) * TT + t1i) * DHH + d] = v1;
                }
            } else {
                *(float2*)&out[(size_t)r0 * DIMM + n] = v0;
                *(float2*)&out[(size_t)(r0 + 8) * DIMM + n] = v1;
            }
        }
    }
}

// ---------------------------------------------------------------------------
// Flash attention (proven R12 config): 8 warps x 16 rows, 256 threads,
// paired q-tiles (one wave), fused Q-rope, exp2 softmax, S C-frag reused
// as PV A-frag, transposed V.
// ---------------------------------------------------------------------------
#define QPAD 72
#define VPAD 72
#define OFF_QH 0
#define OFF_KS (128*QPAD)
#define OFF_VS (OFF_KS + 2*64*QPAD)
#define ATTN_SMEM ((OFF_VS + 2*64*VPAD) * 4)   /* 110592 */

__global__ __launch_bounds__(256, 2) void attn_mma()
{
    extern __shared__ float sm[];
    uint32_t* Qh = (uint32_t*)sm + OFF_QH;
    const uint32_t sb = smem_u32(sm);

    const int bh = blockIdx.y;
    const int tid = threadIdx.x;
    const int wid = tid >> 5;
    const int lane = tid & 31;
    const int gid = lane >> 2;
    const int tg = lane & 3;
    const int wrow = wid * 16;

    const float* Kg = g_k + (size_t)bh * TT * DHH;
    const float* Vg = g_v + (size_t)bh * DHH * TT;   // [d][t]

    const int p0 = kperm8(2 * tg), p1 = kperm8(2 * tg + 1);

#pragma unroll 1
    for (int pass = 0; pass < 2; pass++) {
        const int qt = pass == 0 ? (15 - (int)blockIdx.x) : (int)blockIdx.x;
        const int q0 = qt * 128;
        const float* Qg = g_q + ((size_t)bh * TT + q0) * DHH;

        // Load Q natural, fused RoPE (table), scale, cvt, store d-permuted
#pragma unroll
        for (int i = 0; i < 4; i++) {
            const int e = tid + 256 * i;        // 0..1023
            const int r = e >> 3, j = e & 7;
            const int d0 = j * 4;
            const int t = q0 + r;
            float4 qa = *(const float4*)&Qg[r * DHH + d0];
            float4 qb = *(const float4*)&Qg[r * DHH + 32 + d0];
            float4 cs = *(const float4*)&g_rc[t * 32 + d0];
            float4 sn = *(const float4*)&g_rs[t * 32 + d0];
            float lo[4] = {qa.x * cs.x - qb.x * sn.x, qa.y * cs.y - qb.y * sn.y,
                           qa.z * cs.z - qb.z * sn.z, qa.w * cs.w - qb.w * sn.w};
            float hi[4] = {qa.x * sn.x + qb.x * cs.x, qa.y * sn.y + qb.y * cs.y,
                           qa.z * sn.z + qb.z * cs.z, qa.w * sn.w + qb.w * cs.w};
#pragma unroll
            for (int u = 0; u < 4; u++) {
                const int dd = d0 + u;
                const int dp = (dd & 24) | kperm8(dd & 7);
                Qh[r * QPAD + dp]      = cvt_tf32(lo[u] * QSCALE);
                Qh[r * QPAD + 32 + dp] = cvt_tf32(hi[u] * QSCALE);
            }
        }

        float oacc[8][4];
#pragma unroll
        for (int nf = 0; nf < 8; nf++)
#pragma unroll
            for (int i = 0; i < 4; i++) oacc[nf][i] = 0.f;
        float m0v = -INFINITY, m1v = -INFINITY, l0 = 0.f, l1 = 0.f;

        const int r0g = q0 + wrow + gid;
        const int r1g = r0g + 8;
        const int nkt = 2 * qt + 2;

        auto issue = [&](int kt) {
            const int st = kt & 1;
            const uint32_t kb = sb + (OFF_KS + st * 64 * QPAD) * 4;
            const uint32_t vb = sb + (OFF_VS + st * 64 * VPAD) * 4;
#pragma unroll
            for (int i = 0; i < 4; i++) {
                const int e = tid + 256 * i;
                const int r = e >> 4, c = (e & 15) * 4;
                CP16(kb + (uint32_t)(r * QPAD + c) * 4,
                     &Kg[(size_t)(kt * 64 + r) * DHH + c]);
                CP16(vb + (uint32_t)(r * VPAD + c) * 4,
                     &Vg[(size_t)r * TT + kt * 64 + c]);
            }
            CP_COMMIT();
        };

        issue(0);
        for (int kt = 0; kt < nkt; kt++) {
            if (kt + 1 < nkt) { issue(kt + 1); CP_WAIT1(); }
            else              { CP_WAIT0(); }
            __syncthreads();

            if (kt * 64 <= q0 + wrow + 15) {
                const int st = kt & 1;
                const uint32_t* Ks = (const uint32_t*)sm + OFF_KS + st * 64 * QPAD;
                const uint32_t* Vs = (const uint32_t*)sm + OFF_VS + st * 64 * VPAD;

                float sacc[8][4];
#pragma unroll
                for (int nf = 0; nf < 8; nf++)
#pragma unroll
                    for (int i = 0; i < 4; i++) sacc[nf][i] = 0.f;

#pragma unroll
                for (int ks = 0; ks < 8; ks++) {
                    const int kk = ks * 8 + 2 * tg;
                    const uint32_t* aph = Qh + (wrow + gid) * QPAD + kk;
                    uint2 h0 = *(const uint2*)aph;
                    uint2 h1 = *(const uint2*)(aph + 8 * QPAD);
                    uint32_t ah[4] = {h0.x, h1.x, h0.y, h1.y};
#pragma unroll
                    for (int nf = 0; nf < 8; nf++) {
                        uint2 bv = *(const uint2*)(Ks + (nf * 8 + gid) * QPAD + kk);
                        uint32_t bf[2] = {bv.x, bv.y};
                        mma_tf32(sacc[nf], ah, bf);
                    }
                }

                if (kt >= 2 * qt) {
#pragma unroll
                    for (int nf = 0; nf < 8; nf++) {
                        const int cb = kt * 64 + nf * 8 + 2 * tg;
                        if (cb     > r0g) sacc[nf][0] = -INFINITY;
                        if (cb + 1 > r0g) sacc[nf][1] = -INFINITY;
                        if (cb     > r1g) sacc[nf][2] = -INFINITY;
                        if (cb + 1 > r1g) sacc[nf][3] = -INFINITY;
                    }
                }

                float mx0 = -INFINITY, mx1 = -INFINITY;
#pragma unroll
                for (int nf = 0; nf < 8; nf++) {
                    mx0 = fmaxf(mx0, fmaxf(sacc[nf][0], sacc[nf][1]));
                    mx1 = fmaxf(mx1, fmaxf(sacc[nf][2], sacc[nf][3]));
                }
                mx0 = fmaxf(mx0, __shfl_xor_sync(0xffffffffu, mx0, 1));
                mx0 = fmaxf(mx0, __shfl_xor_sync(0xffffffffu, mx0, 2));
                mx1 = fmaxf(mx1, __shfl_xor_sync(0xffffffffu, mx1, 1));
                mx1 = fmaxf(mx1, __shfl_xor_sync(0xffffffffu, mx1, 2));
                const float mn0 = fmaxf(m0v, mx0), mn1 = fmaxf(m1v, mx1);
                const float c0 = exp2f(m0v - mn0), c1 = exp2f(m1v - mn1);

                float rs0 = 0.f, rs1 = 0.f;
#pragma unroll
                for (int nf = 0; nf < 8; nf++) {
                    sacc[nf][0] = exp2f(sacc[nf][0] - mn0);
                    sacc[nf][1] = exp2f(sacc[nf][1] - mn0);
                    sacc[nf][2] = exp2f(sacc[nf][2] - mn1);
                    sacc[nf][3] = exp2f(sacc[nf][3] - mn1);
                    rs0 += sacc[nf][0] + sacc[nf][1];
                    rs1 += sacc[nf][2] + sacc[nf][3];
                }
                rs0 += __shfl_xor_sync(0xffffffffu, rs0, 1);
                rs0 += __shfl_xor_sync(0xffffffffu, rs0, 2);
                rs1 += __shfl_xor_sync(0xffffffffu, rs1, 1);
                rs1 += __shfl_xor_sync(0xffffffffu, rs1, 2);
                l0 = l0 * c0 + rs0;
                l1 = l1 * c1 + rs1;
                m0v = mn0; m1v = mn1;
#pragma unroll
                for (int nf = 0; nf < 8; nf++) {
                    oacc[nf][0] *= c0; oacc[nf][1] *= c0;
                    oacc[nf][2] *= c1; oacc[nf][3] *= c1;
                }

#pragma unroll
                for (int ks = 0; ks < 8; ks++) {
                    uint32_t af[4] = {cvt_tf32(sacc[ks][0]), cvt_tf32(sacc[ks][2]),
                                      cvt_tf32(sacc[ks][1]), cvt_tf32(sacc[ks][3])};
                    const int kk = ks * 8 + 2 * tg;
#pragma unroll
                    for (int nf = 0; nf < 8; nf++) {
                        uint2 bv = *(const uint2*)(Vs + (nf * 8 + gid) * VPAD + kk);
                        uint32_t bf[2] = {bv.x, bv.y};
                        mma_tf32(oacc[nf], af, bf);
                    }
                }
            }
            __syncthreads();
        }

        const float i0 = 1.f / l0, i1 = 1.f / l1;
        float* Yg = g_y + ((size_t)bh * TT + q0) * DHH;
#pragma unroll
        for (int nf = 0; nf < 8; nf++) {
            float* y0 = &Yg[(wrow + gid) * DHH + nf * 8];
            float* y1 = &Yg[(wrow + gid + 8) * DHH + nf * 8];
            y0[p0] = rnd_tf32(oacc[nf][0] * i0);
            y0[p1] = rnd_tf32(oacc[nf][1] * i0);
            y1[p0] = rnd_tf32(oacc[nf][2] * i1);
            y1[p1] = rnd_tf32(oacc[nf][3] * i1);
        }
        __syncthreads();
    }
}

// ---------------------------------------------------------------------------
extern "C" void kernel_launch(void* const* d_in, const int* in_sizes, int n_in,
                              void* d_out, int out_size)
{
    (void)in_sizes; (void)n_in; (void)out_size;
    const float* x     = (const float*)d_in[0];
    const float* W_qkv = (const float*)d_in[2];
    const float* b_qkv = (const float*)d_in[3];
    const float* W_out = (const float*)d_in[4];
    const float* b_out = (const float*)d_in[5];
    float* out = (float*)d_out;

    cudaFuncSetAttribute(attn_mma,
                         cudaFuncAttributeMaxDynamicSharedMemorySize, ATTN_SMEM);
    cudaFuncSetAttribute(gemm_mma<0>,
                         cudaFuncAttributeMaxDynamicSharedMemorySize, GEMM_SMEM);
    cudaFuncSetAttribute(gemm_mma<1>,
                         cudaFuncAttributeMaxDynamicSharedMemorySize, GEMM_SMEM);

    float* wtq = nullptr; cudaGetSymbolAddress((void**)&wtq, g_wtq);
    float* wto = nullptr; cudaGetSymbolAddress((void**)&wto, g_wto);
    float* xr  = nullptr; cudaGetSymbolAddress((void**)&xr, g_xr);

    // 0) fused prep: rope table + rounded/permuted x + transposed weights
    prep_all<<<2048 + 3072 + 1024 + 256, 256>>>(x, W_qkv, W_out);

    // 1) QKV projection (K rope fused in epilogue; V transposed; q natural)
    gemm_mma<0><<<dim3(3072 / 128, M_TOT / 128), 256, GEMM_SMEM>>>(xr, wtq, b_qkv, nullptr);

    // 2) causal flash attention (paired q-tiles, one wave)
    attn_mma<<<dim3(8, BB * HH), 256, ATTN_SMEM>>>();

    // 3) output projection
    gemm_mma<1><<<dim3(DIMM / 128, M_TOT / 128), 256, GEMM_SMEM>>>(nullptr, wto, b_out, out);
}